// round 6
// baseline (speedup 1.0000x reference)
#include <cuda_runtime.h>
#include <math.h>

// ----------------------------------------------------------------------------
// LayerNormLSTM (2-layer bidirectional LN-LSTM, reference has the
// constant-input-layer-1 aliasing bug), fp32 throughout.
// B=64, S=48, E=512, H=512, 4H=2048. Output [64, 1024] fp32.
//
// kernel_launch contains ONLY kernel launches (no host CUDA APIs at all)
// so the captured graph is pure launch nodes.
// ----------------------------------------------------------------------------

#define EPSF 1e-5f

#define Bn   64
#define Sn   48
#define En   512
#define Hn   512
#define G4n  2048

// --------------------------- scratch (device globals) ------------------------
__device__ float g_xseq[Sn * Bn * En];            // x transposed to [S,B,E]
__device__ float g_G0[2 * Sn * Bn * G4n];         // LN(x @ W_ih0^T), per dir
__device__ float g_G1[2 * Bn * G4n];              // LN(xc @ W_ih1^T), per dir
__device__ float g_z [2 * Bn * G4n];              // raw h @ W_hh^T per step
__device__ float g_h [2 * Bn * Hn];
__device__ float g_c [2 * Bn * Hn];
__device__ float g_xc[Bn * 2 * Hn];

// --------------------------- helpers ----------------------------------------
__device__ __forceinline__ void block_reduce2(float& a, float& b, float* sbuf) {
    int tid = threadIdx.x;
#pragma unroll
    for (int off = 16; off > 0; off >>= 1) {
        a += __shfl_down_sync(0xffffffffu, a, off);
        b += __shfl_down_sync(0xffffffffu, b, off);
    }
    int warp = tid >> 5, lane = tid & 31, nw = blockDim.x >> 5;
    if (lane == 0) { sbuf[warp] = a; sbuf[32 + warp] = b; }
    __syncthreads();
    if (warp == 0) {
        a = (lane < nw) ? sbuf[lane] : 0.f;
        b = (lane < nw) ? sbuf[32 + lane] : 0.f;
#pragma unroll
        for (int off = 16; off > 0; off >>= 1) {
            a += __shfl_down_sync(0xffffffffu, a, off);
            b += __shfl_down_sync(0xffffffffu, b, off);
        }
        if (lane == 0) { sbuf[0] = a; sbuf[32] = b; }
    }
    __syncthreads();
    a = sbuf[0];
    b = sbuf[32];
    __syncthreads();  // protect sbuf reuse
}

// --------------------------- SGEMM body --------------------------------------
// NT SGEMM: C[M,N] = A[M,K] * B[N,K]^T. A, B K-contiguous row-major.
// Uses blockIdx.x -> N tile, blockIdx.y -> M tile.
template <int BM, int BN, int BK, int TM, int TN>
__device__ __forceinline__ void sgemm_nt_body(
    const float* __restrict__ Ad, const float* __restrict__ Bd,
    float* __restrict__ Cd, int M, int N, int K) {
    constexpr int THREADS = (BM / TM) * (BN / TN);

    __shared__ float As[BK][BM];
    __shared__ float Bs[BK][BN];

    const int m0 = blockIdx.y * BM;
    const int n0 = blockIdx.x * BN;
    const int tid = threadIdx.x;
    const int tm = (tid / (BN / TN)) * TM;
    const int tn = (tid % (BN / TN)) * TN;

    float acc[TM][TN];
#pragma unroll
    for (int i = 0; i < TM; i++)
#pragma unroll
        for (int j = 0; j < TN; j++) acc[i][j] = 0.f;

    for (int k0 = 0; k0 < K; k0 += BK) {
        constexpr int AV = BM * BK / 4;
        constexpr int KQ = BK / 4;
#pragma unroll
        for (int v = tid; v < AV; v += THREADS) {
            int row = v / KQ;
            int kq = (v % KQ) * 4;
            float4 t = *(const float4*)(Ad + (size_t)(m0 + row) * K + k0 + kq);
            As[kq + 0][row] = t.x; As[kq + 1][row] = t.y;
            As[kq + 2][row] = t.z; As[kq + 3][row] = t.w;
        }
        constexpr int BV = BN * BK / 4;
#pragma unroll
        for (int v = tid; v < BV; v += THREADS) {
            int row = v / KQ;
            int kq = (v % KQ) * 4;
            float4 t = *(const float4*)(Bd + (size_t)(n0 + row) * K + k0 + kq);
            Bs[kq + 0][row] = t.x; Bs[kq + 1][row] = t.y;
            Bs[kq + 2][row] = t.z; Bs[kq + 3][row] = t.w;
        }
        __syncthreads();
#pragma unroll
        for (int kk = 0; kk < BK; kk++) {
            float a[TM], bfr[TN];
#pragma unroll
            for (int i = 0; i < TM; i++) a[i] = As[kk][tm + i];
#pragma unroll
            for (int j = 0; j < TN; j++) bfr[j] = Bs[kk][tn + j];
#pragma unroll
            for (int i = 0; i < TM; i++)
#pragma unroll
                for (int j = 0; j < TN; j++)
                    acc[i][j] = fmaf(a[i], bfr[j], acc[i][j]);
        }
        __syncthreads();
    }
#pragma unroll
    for (int i = 0; i < TM; i++)
#pragma unroll
        for (int j = 0; j < TN; j++)
            Cd[(size_t)(m0 + tm + i) * N + n0 + tn + j] = acc[i][j];
}

// --------------------------- kernels ----------------------------------------

// x[B,S,E] -> g_xseq[S,B,E]
__global__ void k_transpose(const float* __restrict__ x) {
    int sb = blockIdx.x;          // s*Bn + b
    int s = sb / Bn, b = sb % Bn;
    const float4* src = (const float4*)(x + ((size_t)b * Sn + s) * En);
    float4* dst = (float4*)(g_xseq + (size_t)sb * En);
    dst[threadIdx.x] = src[threadIdx.x];   // 128 threads * float4 = 512 floats
}

// big input GEMM: g_G0[d] = g_xseq @ w_ih0[d]^T  (M=S*B, N=4H, K=E)
__global__ void __launch_bounds__(256)
k_gemm_ih0(const float* __restrict__ w_ih0) {
    const int d = blockIdx.z;
    sgemm_nt_body<128, 128, 16, 8, 8>(
        g_xseq,
        w_ih0 + (size_t)d * G4n * En,
        g_G0 + (size_t)d * (Sn * Bn) * G4n,
        Sn * Bn, G4n, En);
}

// recurrent GEMM: g_z[d] = g_h[d] @ w[d]^T  (M=B, N=4H, K=Hn)
__global__ void __launch_bounds__(256)
k_gemm_hh(const float* __restrict__ w) {
    const int d = blockIdx.z;
    sgemm_nt_body<64, 32, 16, 4, 2>(
        g_h + (size_t)d * Bn * Hn,
        w + (size_t)d * G4n * Hn,
        g_z + (size_t)d * Bn * G4n,
        Bn, G4n, Hn);
}

// layer-1 input GEMM (once): g_z[d] = g_xc @ w_ih1[d]^T  (M=B, N=4H, K=2H)
__global__ void __launch_bounds__(256)
k_gemm_ih1(const float* __restrict__ w_ih1) {
    const int d = blockIdx.z;
    sgemm_nt_body<64, 32, 16, 4, 2>(
        g_xc,
        w_ih1 + (size_t)d * G4n * (2 * Hn),
        g_z + (size_t)d * Bn * G4n,
        Bn, G4n, 2 * Hn);
}

// Row-wise LayerNorm over rows of length 2048.
// which==0: g_G0 -> g_G0 (rows_per_dir = S*B); which==1: g_z -> g_G1 (B).
__global__ void __launch_bounds__(256)
k_ln_rows(int which, const float* __restrict__ gamma,
          const float* __restrict__ beta, int rows_per_dir) {
    __shared__ float sbuf[64];
    int row = blockIdx.x;
    int d = row / rows_per_dir;
    const float* src = (which == 0 ? g_G0 : g_z) + (size_t)row * G4n;
    float* dst = (which == 0 ? g_G0 : g_G1) + (size_t)row * G4n;
    const float* ga = gamma + (size_t)d * G4n;
    const float* be = beta + (size_t)d * G4n;
    int tid = threadIdx.x;
    float v[8];
    float s = 0.f, s2 = 0.f;
#pragma unroll
    for (int i = 0; i < 8; i++) {
        v[i] = src[tid + i * 256];
        s += v[i];
        s2 += v[i] * v[i];
    }
    block_reduce2(s, s2, sbuf);
    float mu = s * (1.f / G4n);
    float var = s2 * (1.f / G4n) - mu * mu;
    var = var < 0.f ? 0.f : var;
    float r = rsqrtf(var + EPSF);
#pragma unroll
    for (int i = 0; i < 8; i++) {
        int idx = tid + i * 256;
        dst[idx] = (v[i] - mu) * r * ga[idx] + be[idx];
    }
}

__global__ void k_zero_state() {
    int i = blockIdx.x * blockDim.x + threadIdx.x;
    if (i < 2 * Bn * Hn) { g_h[i] = 0.f; g_c[i] = 0.f; }
}

// One fused LSTM step for all (dir, batch) rows.
//   gates = g_ih + LN(z; g_hh, b_hh) ; i,f,o = sigmoid ; g = tanh
//   c = f*c + i*g ; h = o * tanh(LN(c; g_ho, b_ho))
// blockIdx = (b, d); 512 threads; thread tid owns gate cols tid + {0..3}*512
// and cell index tid.
__global__ void __launch_bounds__(512)
k_step(int layer0, int k,
       const float* __restrict__ ln_hh_g, const float* __restrict__ ln_hh_b,
       const float* __restrict__ ln_ho_g, const float* __restrict__ ln_ho_b) {
    __shared__ float sbuf[64];
    int d = blockIdx.y;
    int b = blockIdx.x;
    int tid = threadIdx.x;

    const float* z = g_z + ((size_t)d * Bn + b) * G4n;
    const float* gih;
    if (layer0) {
        int t = (d == 0) ? k : (Sn - 1 - k);
        gih = g_G0 + (((size_t)d * Sn + t) * Bn + b) * G4n;
    } else {
        gih = g_G1 + ((size_t)d * Bn + b) * G4n;
    }

    float zv[4];
    float s = 0.f, s2 = 0.f;
#pragma unroll
    for (int i = 0; i < 4; i++) {
        zv[i] = z[tid + i * 512];
        s += zv[i];
        s2 += zv[i] * zv[i];
    }
    block_reduce2(s, s2, sbuf);
    float mu = s * (1.f / G4n);
    float var = s2 * (1.f / G4n) - mu * mu;
    var = var < 0.f ? 0.f : var;
    float r = rsqrtf(var + EPSF);

    float gate[4];
#pragma unroll
    for (int i = 0; i < 4; i++) {
        int gi = tid + i * 512;
        gate[i] = gih[gi] + (zv[i] - mu) * r * ln_hh_g[(size_t)d * G4n + gi]
                  + ln_hh_b[(size_t)d * G4n + gi];
    }
    float ig = 1.f / (1.f + expf(-gate[0]));
    float fg = 1.f / (1.f + expf(-gate[1]));
    float og = 1.f / (1.f + expf(-gate[2]));
    float gg = tanhf(gate[3]);

    float* cp = g_c + ((size_t)d * Bn + b) * Hn;
    float* hp = g_h + ((size_t)d * Bn + b) * Hn;
    float c = fg * cp[tid] + ig * gg;
    cp[tid] = c;

    float cs = c, cs2 = c * c;
    block_reduce2(cs, cs2, sbuf);
    float muc = cs * (1.f / Hn);
    float varc = cs2 * (1.f / Hn) - muc * muc;
    varc = varc < 0.f ? 0.f : varc;
    float rc = rsqrtf(varc + EPSF);

    float hn = og * tanhf((c - muc) * rc * ln_ho_g[(size_t)d * Hn + tid]
                          + ln_ho_b[(size_t)d * Hn + tid]);
    hp[tid] = hn;
}

// xc[b] = concat(h_fwd[b], h_bwd[b])
__global__ void k_build_xc() {
    int b = blockIdx.x, t = threadIdx.x;
    g_xc[(size_t)b * 1024 + t]       = g_h[(size_t)(0 * Bn + b) * Hn + t];
    g_xc[(size_t)b * 1024 + 512 + t] = g_h[(size_t)(1 * Bn + b) * Hn + t];
}

// out[b] = concat(h1_fwd[b], h1_bwd[b])
__global__ void k_out(float* __restrict__ out) {
    int b = blockIdx.x, t = threadIdx.x;
    out[(size_t)b * 1024 + t]       = g_h[(size_t)(0 * Bn + b) * Hn + t];
    out[(size_t)b * 1024 + 512 + t] = g_h[(size_t)(1 * Bn + b) * Hn + t];
}

// --------------------------- launch -----------------------------------------
extern "C" void kernel_launch(void* const* d_in, const int* in_sizes, int n_in,
                              void* d_out, int out_size) {
    (void)in_sizes; (void)n_in; (void)out_size;

    const float* x        = (const float*)d_in[0];
    // d_in[1] = text_length (unused by the reference forward)
    const float* w_ih0    = (const float*)d_in[2];
    const float* w_hh0    = (const float*)d_in[3];
    const float* ln_ih0_g = (const float*)d_in[4];
    const float* ln_ih0_b = (const float*)d_in[5];
    const float* ln_hh0_g = (const float*)d_in[6];
    const float* ln_hh0_b = (const float*)d_in[7];
    const float* ln_ho0_g = (const float*)d_in[8];
    const float* ln_ho0_b = (const float*)d_in[9];
    const float* w_ih1    = (const float*)d_in[10];
    const float* w_hh1    = (const float*)d_in[11];
    const float* ln_ih1_g = (const float*)d_in[12];
    const float* ln_ih1_b = (const float*)d_in[13];
    const float* ln_hh1_g = (const float*)d_in[14];
    const float* ln_hh1_b = (const float*)d_in[15];
    const float* ln_ho1_g = (const float*)d_in[16];
    const float* ln_ho1_b = (const float*)d_in[17];
    float* out = (float*)d_out;

    // ---- phase 1: x transpose + big input GEMM + LN -> g_G0 ----
    k_transpose<<<Sn * Bn, 128>>>(x);
    k_gemm_ih0<<<dim3(G4n / 128, (Sn * Bn) / 128, 2), 256>>>(w_ih0);
    k_ln_rows<<<2 * Sn * Bn, 256>>>(0, ln_ih0_g, ln_ih0_b, Sn * Bn);

    // ---- layer 0 recurrence (both directions batched in gridDim.z) ----
    k_zero_state<<<(2 * Bn * Hn + 255) / 256, 256>>>();
    for (int k = 0; k < Sn; k++) {
        k_gemm_hh<<<dim3(G4n / 32, 1, 2), 256>>>(w_hh0);
        k_step<<<dim3(Bn, 2), 512>>>(1, k, ln_hh0_g, ln_hh0_b,
                                     ln_ho0_g, ln_ho0_b);
    }

    // ---- layer 1 constant input: xc -> LN(xc @ W_ih1^T) once ----
    k_build_xc<<<Bn, 512>>>();
    k_gemm_ih1<<<dim3(G4n / 32, 1, 2), 256>>>(w_ih1);
    k_ln_rows<<<2 * Bn, 256>>>(1, ln_ih1_g, ln_ih1_b, Bn);

    // ---- layer 1 recurrence ----
    k_zero_state<<<(2 * Bn * Hn + 255) / 256, 256>>>();
    for (int k = 0; k < Sn; k++) {
        k_gemm_hh<<<dim3(G4n / 32, 1, 2), 256>>>(w_hh1);
        k_step<<<dim3(Bn, 2), 512>>>(0, k, ln_hh1_g, ln_hh1_b,
                                     ln_ho1_g, ln_ho1_b);
    }

    // ---- output ----
    k_out<<<Bn, 512>>>(out);
}

// round 12
// speedup vs baseline: 1.0335x; 1.0335x over previous
#include <cuda_runtime.h>
#include <math.h>

// ----------------------------------------------------------------------------
// LayerNormLSTM, fp32. B=64, S=48, E=512, H=512, 4H=2048. Output [64,1024].
// Structure:
//   phase-1: transpose + big f32x2 GEMM LN(x @ W_ih0^T) -> g_G0
//   layer0:  ONE persistent kernel runs all 48 steps (both dirs) with
//            atomic grid barriers (128 blocks, guaranteed co-resident).
//   layer1:  constant-input bug exploited (input GEMM once), same persistent
//            recurrence kernel.
// ----------------------------------------------------------------------------

#define EPSF 1e-5f
#define Bn   64
#define Sn   48
#define En   512
#define Hn   512
#define G4n  2048

// --------------------------- scratch (device globals) ------------------------
__device__ float g_xseq[Sn * Bn * En];
__device__ float g_G0[2 * Sn * Bn * G4n];
__device__ float g_G1[2 * Bn * G4n];
__device__ float g_z [2 * Bn * G4n];
__device__ float g_h [2 * Bn * Hn];
__device__ float g_c [2 * Bn * Hn];
__device__ float g_xc[Bn * 2 * Hn];
__device__ unsigned g_barcnt = 0;
__device__ unsigned g_bargen = 0;

// --------------------------- packed fp32x2 FMA --------------------------------
union F2U { float2 f; unsigned long long u; };
__device__ __forceinline__ float2 ffma2(float2 a, float2 b, float2 c) {
    F2U ua, ub, uc, ud;
    ua.f = a; ub.f = b; uc.f = c;
    asm("fma.rn.f32x2 %0, %1, %2, %3;"
        : "=l"(ud.u) : "l"(ua.u), "l"(ub.u), "l"(uc.u));
    return ud.f;
}

// --------------------------- helpers ----------------------------------------
__device__ __forceinline__ void block_reduce2(float& a, float& b, float* sbuf) {
    int tid = threadIdx.x;
#pragma unroll
    for (int off = 16; off > 0; off >>= 1) {
        a += __shfl_down_sync(0xffffffffu, a, off);
        b += __shfl_down_sync(0xffffffffu, b, off);
    }
    int warp = tid >> 5, lane = tid & 31, nw = blockDim.x >> 5;
    if (lane == 0) { sbuf[warp] = a; sbuf[32 + warp] = b; }
    __syncthreads();
    if (warp == 0) {
        a = (lane < nw) ? sbuf[lane] : 0.f;
        b = (lane < nw) ? sbuf[32 + lane] : 0.f;
#pragma unroll
        for (int off = 16; off > 0; off >>= 1) {
            a += __shfl_down_sync(0xffffffffu, a, off);
            b += __shfl_down_sync(0xffffffffu, b, off);
        }
        if (lane == 0) { sbuf[0] = a; sbuf[32] = b; }
    }
    __syncthreads();
    a = sbuf[0];
    b = sbuf[32];
    __syncthreads();
}

// Grid-wide barrier. Safe: all 128 blocks are co-resident (128 <= 148 SMs,
// 1 CTA/SM fits easily). Nanosleep backoff keeps the L2 atomic slice cool.
__device__ __forceinline__ void grid_bar(unsigned nb) {
    __syncthreads();
    if (threadIdx.x == 0) {
        unsigned gen = *(volatile unsigned*)&g_bargen;
        __threadfence();
        unsigned t = atomicAdd(&g_barcnt, 1u);
        if (t == nb - 1u) {
            atomicExch(&g_barcnt, 0u);
            __threadfence();
            atomicAdd(&g_bargen, 1u);
        } else {
            while (*(volatile unsigned*)&g_bargen == gen) { __nanosleep(64); }
        }
        __threadfence();
    }
    __syncthreads();
}

// --------------------------- scalar SGEMM (small, ih1 only) -------------------
template <int BM, int BN, int BK, int TM, int TN>
__device__ __forceinline__ void sgemm_nt_body(
    const float* __restrict__ Ad, const float* __restrict__ Bd,
    float* __restrict__ Cd, int M, int N, int K) {
    constexpr int THREADS = (BM / TM) * (BN / TN);
    __shared__ float As[BK][BM];
    __shared__ float Bs[BK][BN];
    const int m0 = blockIdx.y * BM;
    const int n0 = blockIdx.x * BN;
    const int tid = threadIdx.x;
    const int tm = (tid / (BN / TN)) * TM;
    const int tn = (tid % (BN / TN)) * TN;
    float acc[TM][TN];
#pragma unroll
    for (int i = 0; i < TM; i++)
#pragma unroll
        for (int j = 0; j < TN; j++) acc[i][j] = 0.f;
    for (int k0 = 0; k0 < K; k0 += BK) {
        constexpr int AV = BM * BK / 4;
        constexpr int KQ = BK / 4;
#pragma unroll
        for (int v = tid; v < AV; v += THREADS) {
            int row = v / KQ, kq = (v % KQ) * 4;
            float4 t = *(const float4*)(Ad + (size_t)(m0 + row) * K + k0 + kq);
            As[kq + 0][row] = t.x; As[kq + 1][row] = t.y;
            As[kq + 2][row] = t.z; As[kq + 3][row] = t.w;
        }
        constexpr int BV = BN * BK / 4;
#pragma unroll
        for (int v = tid; v < BV; v += THREADS) {
            int row = v / KQ, kq = (v % KQ) * 4;
            float4 t = *(const float4*)(Bd + (size_t)(n0 + row) * K + k0 + kq);
            Bs[kq + 0][row] = t.x; Bs[kq + 1][row] = t.y;
            Bs[kq + 2][row] = t.z; Bs[kq + 3][row] = t.w;
        }
        __syncthreads();
#pragma unroll
        for (int kk = 0; kk < BK; kk++) {
            float a[TM], bfr[TN];
#pragma unroll
            for (int i = 0; i < TM; i++) a[i] = As[kk][tm + i];
#pragma unroll
            for (int j = 0; j < TN; j++) bfr[j] = Bs[kk][tn + j];
#pragma unroll
            for (int i = 0; i < TM; i++)
#pragma unroll
                for (int j = 0; j < TN; j++)
                    acc[i][j] = fmaf(a[i], bfr[j], acc[i][j]);
        }
        __syncthreads();
    }
#pragma unroll
    for (int i = 0; i < TM; i++)
#pragma unroll
        for (int j = 0; j < TN; j++)
            Cd[(size_t)(m0 + tm + i) * N + n0 + tn + j] = acc[i][j];
}

// --------------------------- kernels ----------------------------------------

// x[B,S,E] -> g_xseq[S,B,E]
__global__ void k_transpose(const float* __restrict__ x) {
    int sb = blockIdx.x;
    int s = sb / Bn, b = sb % Bn;
    const float4* src = (const float4*)(x + ((size_t)b * Sn + s) * En);
    float4* dst = (float4*)(g_xseq + (size_t)sb * En);
    dst[threadIdx.x] = src[threadIdx.x];
}

// Phase-1 big GEMM with packed f32x2 FMA.
// C[3072,2048] = xseq[3072,512] @ W[d][2048,512]^T per dir.
// 128x128x16 tile, 256 threads, per-thread 8m x 8n (4 float2 pairs along n).
__global__ void __launch_bounds__(256)
k_gemm_ih0(const float* __restrict__ w) {
    __shared__ float2 As2[16][129];   // duplicated A: {a,a}
    __shared__ float  Bs[16][132];
    const int d = blockIdx.z;
    const float* Ad = g_xseq;
    const float* Bd = w + (size_t)d * G4n * En;
    float* Cd = g_G0 + (size_t)d * (Sn * Bn) * G4n;
    const int m0 = blockIdx.y * 128, n0 = blockIdx.x * 128;
    const int tid = threadIdx.x;
    const int mg = tid >> 4, ng = tid & 15;

    float2 acc[8][4];
#pragma unroll
    for (int i = 0; i < 8; i++)
#pragma unroll
        for (int j = 0; j < 4; j++) acc[i][j] = make_float2(0.f, 0.f);

    float4 av[2], bv[2];
    // preload chunk 0
    {
#pragma unroll
        for (int t = 0; t < 2; t++) {
            int v = tid + 256 * t;
            int m = v >> 2, kk = (v & 3) * 4;
            av[t] = *(const float4*)(Ad + (size_t)(m0 + m) * En + kk);
            bv[t] = *(const float4*)(Bd + (size_t)(n0 + m) * En + kk);
        }
    }
    for (int kc = 0; kc < 32; kc++) {
#pragma unroll
        for (int t = 0; t < 2; t++) {
            int v = tid + 256 * t;
            int m = v >> 2, kk = (v & 3) * 4;
            As2[kk + 0][m] = make_float2(av[t].x, av[t].x);
            As2[kk + 1][m] = make_float2(av[t].y, av[t].y);
            As2[kk + 2][m] = make_float2(av[t].z, av[t].z);
            As2[kk + 3][m] = make_float2(av[t].w, av[t].w);
            Bs[kk + 0][m] = bv[t].x;
            Bs[kk + 1][m] = bv[t].y;
            Bs[kk + 2][m] = bv[t].z;
            Bs[kk + 3][m] = bv[t].w;
        }
        __syncthreads();
        if (kc < 31) {
            int k0 = (kc + 1) * 16;
#pragma unroll
            for (int t = 0; t < 2; t++) {
                int v = tid + 256 * t;
                int m = v >> 2, kk = (v & 3) * 4;
                av[t] = *(const float4*)(Ad + (size_t)(m0 + m) * En + k0 + kk);
                bv[t] = *(const float4*)(Bd + (size_t)(n0 + m) * En + k0 + kk);
            }
        }
#pragma unroll
        for (int kk = 0; kk < 16; kk++) {
            float2 a[8], wv[4];
#pragma unroll
            for (int i = 0; i < 8; i++) a[i] = As2[kk][mg + 16 * i];
#pragma unroll
            for (int j = 0; j < 4; j++)
                wv[j] = *(const float2*)&Bs[kk][2 * ng + 32 * j];
#pragma unroll
            for (int i = 0; i < 8; i++)
#pragma unroll
                for (int j = 0; j < 4; j++)
                    acc[i][j] = ffma2(a[i], wv[j], acc[i][j]);
        }
        __syncthreads();
    }
#pragma unroll
    for (int i = 0; i < 8; i++)
#pragma unroll
        for (int j = 0; j < 4; j++)
            *(float2*)(Cd + (size_t)(m0 + mg + 16 * i) * G4n + n0 + 2 * ng + 32 * j)
                = acc[i][j];
}

// layer-1 input GEMM (once): g_z[d] = g_xc @ w_ih1[d]^T
__global__ void __launch_bounds__(256)
k_gemm_ih1(const float* __restrict__ w_ih1) {
    const int d = blockIdx.z;
    sgemm_nt_body<64, 32, 16, 4, 2>(
        g_xc, w_ih1 + (size_t)d * G4n * (2 * Hn),
        g_z + (size_t)d * Bn * G4n, Bn, G4n, 2 * Hn);
}

// Row-wise LayerNorm over rows of length 2048.
__global__ void __launch_bounds__(256)
k_ln_rows(int which, const float* __restrict__ gamma,
          const float* __restrict__ beta, int rows_per_dir) {
    __shared__ float sbuf[64];
    int row = blockIdx.x;
    int d = row / rows_per_dir;
    const float* src = (which == 0 ? g_G0 : g_z) + (size_t)row * G4n;
    float* dst = (which == 0 ? g_G0 : g_G1) + (size_t)row * G4n;
    const float* ga = gamma + (size_t)d * G4n;
    const float* be = beta + (size_t)d * G4n;
    int tid = threadIdx.x;
    float v[8];
    float s = 0.f, s2 = 0.f;
#pragma unroll
    for (int i = 0; i < 8; i++) {
        v[i] = src[tid + i * 256];
        s += v[i];
        s2 += v[i] * v[i];
    }
    block_reduce2(s, s2, sbuf);
    float mu = s * (1.f / G4n);
    float var = s2 * (1.f / G4n) - mu * mu;
    var = var < 0.f ? 0.f : var;
    float r = rsqrtf(var + EPSF);
#pragma unroll
    for (int i = 0; i < 8; i++) {
        int idx = tid + i * 256;
        dst[idx] = (v[i] - mu) * r * ga[idx] + be[idx];
    }
}

// --------------------------- persistent recurrence ---------------------------
// 128 blocks x 256 threads. Runs all 48 steps of one layer (both dirs).
// Phase G: block (d, q) computes z[d, all b, q*32 .. q*32+31] = h @ W^T slice.
// Phase S: block (d, b) does the fused LN/LSTM cell update for its row.
// Two grid barriers per step. Mutable cross-phase data read via __ldcg.
__global__ void __launch_bounds__(256)
k_recur(int layer0, const float* __restrict__ W,
        const float* __restrict__ ln_hh_g, const float* __restrict__ ln_hh_b,
        const float* __restrict__ ln_ho_g, const float* __restrict__ ln_ho_b) {
    __shared__ float2 As2[32][65];   // duplicated h: {h,h}, (kk, b)
    __shared__ float  Bs[32][34];    // W slice, (kk, n)
    __shared__ float  sbuf[64];

    const int r = blockIdx.x;        // 0..127
    const int tid = threadIdx.x;
    const int d = r >> 6, q = r & 63;

    // init h = c = 0 for this block's (d,q) row
    g_h[(size_t)(d * Bn + q) * Hn + tid] = 0.f;
    g_h[(size_t)(d * Bn + q) * Hn + tid + 256] = 0.f;
    g_c[(size_t)(d * Bn + q) * Hn + tid] = 0.f;
    g_c[(size_t)(d * Bn + q) * Hn + tid + 256] = 0.f;
    grid_bar(128);

    const float* Wd = W + (size_t)d * G4n * Hn + (size_t)(q * 32) * Hn;
    const float* hsrc = g_h + (size_t)d * Bn * Hn;   // [64][512]
    const int bg = tid >> 3;       // 0..31 -> b = bg, bg+32
    const int ng = tid & 7;        // n pairs at 2ng, 2ng+16

    const float* GA = ln_hh_g + (size_t)d * G4n;
    const float* BA = ln_hh_b + (size_t)d * G4n;
    const float* GO = ln_ho_g + (size_t)d * Hn;
    const float* BO = ln_ho_b + (size_t)d * Hn;

    for (int step = 0; step < Sn; step++) {
        // ================= phase G: z slice = h @ W^T ====================
        {
            float2 acc[2][2];
#pragma unroll
            for (int i = 0; i < 2; i++)
#pragma unroll
                for (int j = 0; j < 2; j++) acc[i][j] = make_float2(0.f, 0.f);

            float4 hv[2], wv;
            // preload chunk 0 (h is mutable across steps -> __ldcg)
            {
#pragma unroll
                for (int t = 0; t < 2; t++) {
                    int v = tid + 256 * t;        // 0..511
                    int b = v >> 3, kk = (v & 7) * 4;
                    hv[t] = __ldcg((const float4*)(hsrc + (size_t)b * Hn + kk));
                }
                int n = tid >> 3, kk = (tid & 7) * 4;
                wv = *(const float4*)(Wd + (size_t)n * Hn + kk);
            }
            for (int kc = 0; kc < 16; kc++) {
#pragma unroll
                for (int t = 0; t < 2; t++) {
                    int v = tid + 256 * t;
                    int b = v >> 3, kk = (v & 7) * 4;
                    As2[kk + 0][b] = make_float2(hv[t].x, hv[t].x);
                    As2[kk + 1][b] = make_float2(hv[t].y, hv[t].y);
                    As2[kk + 2][b] = make_float2(hv[t].z, hv[t].z);
                    As2[kk + 3][b] = make_float2(hv[t].w, hv[t].w);
                }
                {
                    int n = tid >> 3, kk = (tid & 7) * 4;
                    Bs[kk + 0][n] = wv.x;
                    Bs[kk + 1][n] = wv.y;
                    Bs[kk + 2][n] = wv.z;
                    Bs[kk + 3][n] = wv.w;
                }
                __syncthreads();
                if (kc < 15) {
                    int k0 = (kc + 1) * 32;
#pragma unroll
                    for (int t = 0; t < 2; t++) {
                        int v = tid + 256 * t;
                        int b = v >> 3, kk = (v & 7) * 4;
                        hv[t] = __ldcg((const float4*)(hsrc + (size_t)b * Hn + k0 + kk));
                    }
                    int n = tid >> 3, kk = (tid & 7) * 4;
                    wv = *(const float4*)(Wd + (size_t)n * Hn + k0 + kk);
                }
#pragma unroll
                for (int kk = 0; kk < 32; kk++) {
                    float2 a0 = As2[kk][bg];
                    float2 a1 = As2[kk][bg + 32];
                    float2 w0 = *(const float2*)&Bs[kk][2 * ng];
                    float2 w1 = *(const float2*)&Bs[kk][2 * ng + 16];
                    acc[0][0] = ffma2(a0, w0, acc[0][0]);
                    acc[0][1] = ffma2(a0, w1, acc[0][1]);
                    acc[1][0] = ffma2(a1, w0, acc[1][0]);
                    acc[1][1] = ffma2(a1, w1, acc[1][1]);
                }
                __syncthreads();
            }
#pragma unroll
            for (int i = 0; i < 2; i++) {
                int b = bg + 32 * i;
                float* zrow = g_z + (size_t)(d * Bn + b) * G4n + q * 32;
                *(float2*)(zrow + 2 * ng) = acc[i][0];
                *(float2*)(zrow + 2 * ng + 16) = acc[i][1];
            }
        }
        __threadfence();
        grid_bar(128);

        // ================= phase S: fused LN/LSTM cell ===================
        {
            const float* zrow = g_z + (size_t)(d * Bn + q) * G4n;
            const float* gih;
            if (layer0) {
                int t = (d == 0) ? step : (Sn - 1 - step);
                gih = g_G0 + (((size_t)d * Sn + t) * Bn + q) * G4n;
            } else {
                gih = g_G1 + ((size_t)d * Bn + q) * G4n;
            }

            float zv[8];
            float s = 0.f, s2 = 0.f;
#pragma unroll
            for (int i = 0; i < 8; i++) {
                zv[i] = __ldcg(zrow + tid + i * 256);
                s += zv[i];
                s2 += zv[i] * zv[i];
            }
            block_reduce2(s, s2, sbuf);
            float mu = s * (1.f / G4n);
            float var = s2 * (1.f / G4n) - mu * mu;
            var = var < 0.f ? 0.f : var;
            float rinv = rsqrtf(var + EPSF);

            float cv[2], og[2];
#pragma unroll
            for (int u = 0; u < 2; u++) {
                int j = tid + u * 256;
                float g0 = gih[j]        + (zv[0 + u] - mu) * rinv * GA[j]        + BA[j];
                float g1 = gih[j + 512]  + (zv[2 + u] - mu) * rinv * GA[j + 512]  + BA[j + 512];
                float g2 = gih[j + 1024] + (zv[4 + u] - mu) * rinv * GA[j + 1024] + BA[j + 1024];
                float g3 = gih[j + 1536] + (zv[6 + u] - mu) * rinv * GA[j + 1536] + BA[j + 1536];
                float ig = 1.f / (1.f + expf(-g0));
                float fg = 1.f / (1.f + expf(-g1));
                og[u]    = 1.f / (1.f + expf(-g2));
                float gg = tanhf(g3);
                size_t cidx = (size_t)(d * Bn + q) * Hn + j;
                float c = fg * __ldcg(&g_c[cidx]) + ig * gg;
                g_c[cidx] = c;
                cv[u] = c;
            }
            float cs = cv[0] + cv[1];
            float cs2 = cv[0] * cv[0] + cv[1] * cv[1];
            block_reduce2(cs, cs2, sbuf);
            float muc = cs * (1.f / Hn);
            float varc = cs2 * (1.f / Hn) - muc * muc;
            varc = varc < 0.f ? 0.f : varc;
            float rc = rsqrtf(varc + EPSF);
#pragma unroll
            for (int u = 0; u < 2; u++) {
                int j = tid + u * 256;
                float hn = og[u] * tanhf((cv[u] - muc) * rc * GO[j] + BO[j]);
                g_h[(size_t)(d * Bn + q) * Hn + j] = hn;
            }
        }
        __threadfence();
        grid_bar(128);
    }
}

// xc[b] = concat(h_fwd[b], h_bwd[b])
__global__ void k_build_xc() {
    int b = blockIdx.x, t = threadIdx.x;
    g_xc[(size_t)b * 1024 + t]       = g_h[(size_t)(0 * Bn + b) * Hn + t];
    g_xc[(size_t)b * 1024 + 512 + t] = g_h[(size_t)(1 * Bn + b) * Hn + t];
}

__global__ void k_out(float* __restrict__ out) {
    int b = blockIdx.x, t = threadIdx.x;
    out[(size_t)b * 1024 + t]       = g_h[(size_t)(0 * Bn + b) * Hn + t];
    out[(size_t)b * 1024 + 512 + t] = g_h[(size_t)(1 * Bn + b) * Hn + t];
}

// --------------------------- launch -----------------------------------------
extern "C" void kernel_launch(void* const* d_in, const int* in_sizes, int n_in,
                              void* d_out, int out_size) {
    (void)in_sizes; (void)n_in; (void)out_size;

    const float* x        = (const float*)d_in[0];
    const float* w_ih0    = (const float*)d_in[2];
    const float* w_hh0    = (const float*)d_in[3];
    const float* ln_ih0_g = (const float*)d_in[4];
    const float* ln_ih0_b = (const float*)d_in[5];
    const float* ln_hh0_g = (const float*)d_in[6];
    const float* ln_hh0_b = (const float*)d_in[7];
    const float* ln_ho0_g = (const float*)d_in[8];
    const float* ln_ho0_b = (const float*)d_in[9];
    const float* w_ih1    = (const float*)d_in[10];
    const float* w_hh1    = (const float*)d_in[11];
    const float* ln_ih1_g = (const float*)d_in[12];
    const float* ln_ih1_b = (const float*)d_in[13];
    const float* ln_hh1_g = (const float*)d_in[14];
    const float* ln_hh1_b = (const float*)d_in[15];
    const float* ln_ho1_g = (const float*)d_in[16];
    const float* ln_ho1_b = (const float*)d_in[17];
    float* out = (float*)d_out;

    // ---- phase 1 ----
    k_transpose<<<Sn * Bn, 128>>>(x);
    k_gemm_ih0<<<dim3(G4n / 128, (Sn * Bn) / 128, 2), 256>>>(w_ih0);
    k_ln_rows<<<2 * Sn * Bn, 256>>>(0, ln_ih0_g, ln_ih0_b, Sn * Bn);

    // ---- layer 0: persistent recurrence ----
    k_recur<<<128, 256>>>(1, w_hh0, ln_hh0_g, ln_hh0_b, ln_ho0_g, ln_ho0_b);

    // ---- layer 1 constant input ----
    k_build_xc<<<Bn, 512>>>();
    k_gemm_ih1<<<dim3(G4n / 32, 1, 2), 256>>>(w_ih1);
    k_ln_rows<<<2 * Bn, 256>>>(1, ln_ih1_g, ln_ih1_b, Bn);

    // ---- layer 1: persistent recurrence ----
    k_recur<<<128, 256>>>(0, w_hh1, ln_hh1_g, ln_hh1_b, ln_ho1_g, ln_ho1_b);

    // ---- output ----
    k_out<<<Bn, 512>>>(out);
}